// round 9
// baseline (speedup 1.0000x reference)
#include <cuda_runtime.h>
#include <cuda_bf16.h>
#include <math.h>
#include <stdint.h>

// ---------------- problem constants ----------------
#define D_MODEL  768
#define N_LAYERS 2
#define D_STATE  16
#define VOCAB    32000
#define D_INNER  1536            // 2*D_MODEL
#define BATCH    2
#define SEQ      2048
#define NTOK     (BATCH*SEQ)     // 4096
#define LN_EPS   1e-5f

// ---------------- scratch (device globals; no mallocs allowed) ----------------
__device__ static float g_x [NTOK * D_MODEL];
__device__ static float g_xp[NTOK * 2 * D_INNER];
__device__ static float g_dt[NTOK * D_INNER];
__device__ static float g_Bm[NTOK * D_STATE];
__device__ static float g_Cm[NTOK * D_STATE];
__device__ static float g_y [NTOK * D_INNER];
__device__ static float g_o [NTOK * D_MODEL];
// bf16 split operands (dedicated buffer per tensor)
__device__ static __nv_bfloat16 g_xhi[NTOK * D_MODEL];
__device__ static __nv_bfloat16 g_xlo[NTOK * D_MODEL];
__device__ static __nv_bfloat16 g_yhi[NTOK * D_INNER];
__device__ static __nv_bfloat16 g_ylo[NTOK * D_INNER];
__device__ static __nv_bfloat16 g_wihi[N_LAYERS * 2 * D_INNER * D_MODEL];
__device__ static __nv_bfloat16 g_wilo[N_LAYERS * 2 * D_INNER * D_MODEL];
__device__ static __nv_bfloat16 g_wdhi[N_LAYERS * D_INNER * D_MODEL];
__device__ static __nv_bfloat16 g_wdlo[N_LAYERS * D_INNER * D_MODEL];
__device__ static __nv_bfloat16 g_wohi[N_LAYERS * D_MODEL * D_INNER];
__device__ static __nv_bfloat16 g_wolo[N_LAYERS * D_MODEL * D_INNER];
__device__ static __nv_bfloat16 g_ehi[VOCAB * D_MODEL];
__device__ static __nv_bfloat16 g_elo[VOCAB * D_MODEL];

// ======================= helpers =======================
__device__ __forceinline__ uint32_t s2u(const void* p) {
    uint32_t a;
    asm("{ .reg .u64 t; cvta.to.shared.u64 t, %1; cvt.u32.u64 %0, t; }"
        : "=r"(a) : "l"(p));
    return a;
}

__device__ __forceinline__ void ldsm4(uint32_t* r, uint32_t addr) {
    asm volatile("ldmatrix.sync.aligned.m8n8.x4.shared.b16 {%0,%1,%2,%3}, [%4];"
                 : "=r"(r[0]), "=r"(r[1]), "=r"(r[2]), "=r"(r[3]) : "r"(addr));
}

__device__ __forceinline__ void mma_bf16(float* c, const uint32_t* a,
                                         uint32_t b0, uint32_t b1) {
    asm volatile(
        "mma.sync.aligned.m16n8k16.row.col.f32.bf16.bf16.f32 "
        "{%0,%1,%2,%3}, {%4,%5,%6,%7}, {%8,%9}, {%0,%1,%2,%3};"
        : "+f"(c[0]), "+f"(c[1]), "+f"(c[2]), "+f"(c[3])
        : "r"(a[0]), "r"(a[1]), "r"(a[2]), "r"(a[3]), "r"(b0), "r"(b1));
}

__device__ __forceinline__ void cp16(uint32_t saddr, const void* gaddr) {
    asm volatile("cp.async.ca.shared.global [%0], [%1], 16;"
                 :: "r"(saddr), "l"(gaddr) : "memory");
}

// =================== split-bf16 tensor GEMM: C = A @ B^T ===================
// A [M,K], B [N,K] as (hi, lo) bf16 pairs. Tile 128x128, K-chunk 32.
// C = Ahi@Bhi + Ahi@Blo + Alo@Bhi in fp32 accumulators (HMMA mma.sync;
// tcgen05 unavailable — harness PTX target is compute_103 non-'a').
// 3-stage cp.async pipeline, 32KB/stage (4 operands x 8KB, 64B rows, SW64),
// 96KB total -> STILL 2 CTAs/SM. Depth without the round-7 occupancy loss.
#define KCH    32
#define ST_A_H 0
#define ST_A_L 8192
#define ST_B_H 16384
#define ST_B_L 24576
#define STG_SZ 32768
#define NSTG   3
#define GEMM_SMEM (NSTG * STG_SZ)     // 98304

__global__ void __launch_bounds__(256, 2)
gemm_split(const __nv_bfloat16* __restrict__ Ahi, const __nv_bfloat16* __restrict__ Alo,
           const __nv_bfloat16* __restrict__ Bhi, const __nv_bfloat16* __restrict__ Blo,
           float* __restrict__ C, int M, int N, int K,
           int mode, const float* __restrict__ eb1, const float* __restrict__ eb2) {
    extern __shared__ char smc[];
    const uint32_t sb = s2u(smc);
    const int tid = threadIdx.x;
    const int wid = tid >> 5, lid = tid & 31;
    const int wm = wid & 1, wn = wid >> 1;          // warp grid 2(M) x 4(N)
    const int bm = blockIdx.x * 128, bn = blockIdx.y * 128;

    // ---- ldmatrix lane geometry (64B rows, SW64: xor bits[5:4] by row bits[2:1]) ----
    const int rin = lid & 7;
    const uint32_t xr2 = (uint32_t)(rin & 6) << 3;   // swizzle xor (same for A and B)
    const int amat = lid >> 3;
    const uint32_t aKq = (uint32_t)(amat >> 1) * 16; // A k-half byte sel
    uint32_t aTile[4];
#pragma unroll
    for (int mt = 0; mt < 4; mt++)
        aTile[mt] = (uint32_t)(wm * 64 + mt * 16 + (amat & 1) * 8 + rin) * 64;
    const int bpair = lid >> 4, bsub = (lid >> 3) & 1;
    const uint32_t bKq = (uint32_t)bsub * 16;
    uint32_t bTile[2];
#pragma unroll
    for (int p = 0; p < 2; p++)
        bTile[p] = (uint32_t)(wn * 32 + p * 16 + bpair * 8 + rin) * 64;

    // ---- global->smem geometry: 8KB/operand/chunk, 2 x 16B per thread ----
    const int grow = tid >> 1;              // 0..127
    const int gseg = (tid & 1) * 32;        // byte base within 64B row
    uint32_t sOff[2];
#pragma unroll
    for (int j = 0; j < 2; j++) {
        uint32_t o = (uint32_t)grow * 64 + gseg + j * 16;
        sOff[j] = o ^ ((o >> 3) & 0x30);
    }
    const __nv_bfloat16* gAh = Ahi + (size_t)(bm + grow) * K + (tid & 1) * 16;
    const __nv_bfloat16* gAl = Alo + (size_t)(bm + grow) * K + (tid & 1) * 16;
    const __nv_bfloat16* gBh = Bhi + (size_t)(bn + grow) * K + (tid & 1) * 16;
    const __nv_bfloat16* gBl = Blo + (size_t)(bn + grow) * K + (tid & 1) * 16;

    float acc[4][4][4];
#pragma unroll
    for (int mt = 0; mt < 4; mt++)
#pragma unroll
        for (int nt = 0; nt < 4; nt++)
#pragma unroll
            for (int i = 0; i < 4; i++) acc[mt][nt][i] = 0.f;

    const int NC = K / KCH;

    // prologue: chunks 0 and 1 into stages 0 and 1
#pragma unroll
    for (int c = 0; c < 2; c++) {
        const uint32_t st = sb + (uint32_t)c * STG_SZ;
        const int k0 = c * KCH;
#pragma unroll
        for (int j = 0; j < 2; j++) {
            cp16(st + ST_A_H + sOff[j], gAh + k0 + j * 8);
            cp16(st + ST_A_L + sOff[j], gAl + k0 + j * 8);
            cp16(st + ST_B_H + sOff[j], gBh + k0 + j * 8);
            cp16(st + ST_B_L + sOff[j], gBl + k0 + j * 8);
        }
        asm volatile("cp.async.commit_group;" ::: "memory");
    }

    int stg = 0;                            // = c % NSTG
    for (int c = 0; c < NC; c++) {
        asm volatile("cp.async.wait_group 1;" ::: "memory");
        __syncthreads();

        const uint32_t st = sb + (uint32_t)stg * STG_SZ;
#pragma unroll
        for (int ks = 0; ks < 2; ks++) {
            const uint32_t akey = ((uint32_t)ks * 32 + aKq) ^ xr2;
            const uint32_t bkey = ((uint32_t)ks * 32 + bKq) ^ xr2;
            uint32_t ah[4][4], bb[2][4];
            // combo 1: Ahi x Bhi
#pragma unroll
            for (int mt = 0; mt < 4; mt++)
                ldsm4(ah[mt], st + ST_A_H + aTile[mt] + akey);
#pragma unroll
            for (int p = 0; p < 2; p++)
                ldsm4(bb[p], st + ST_B_H + bTile[p] + bkey);
#pragma unroll
            for (int mt = 0; mt < 4; mt++)
#pragma unroll
                for (int nt = 0; nt < 4; nt++)
                    mma_bf16(acc[mt][nt], ah[mt],
                             bb[nt >> 1][(nt & 1) * 2], bb[nt >> 1][(nt & 1) * 2 + 1]);
            // combo 2: Ahi x Blo (reuse ah)
#pragma unroll
            for (int p = 0; p < 2; p++)
                ldsm4(bb[p], st + ST_B_L + bTile[p] + bkey);
#pragma unroll
            for (int mt = 0; mt < 4; mt++)
#pragma unroll
                for (int nt = 0; nt < 4; nt++)
                    mma_bf16(acc[mt][nt], ah[mt],
                             bb[nt >> 1][(nt & 1) * 2], bb[nt >> 1][(nt & 1) * 2 + 1]);
            // combo 3: Alo x Bhi
#pragma unroll
            for (int mt = 0; mt < 4; mt++)
                ldsm4(ah[mt], st + ST_A_L + aTile[mt] + akey);
#pragma unroll
            for (int p = 0; p < 2; p++)
                ldsm4(bb[p], st + ST_B_H + bTile[p] + bkey);
#pragma unroll
            for (int mt = 0; mt < 4; mt++)
#pragma unroll
                for (int nt = 0; nt < 4; nt++)
                    mma_bf16(acc[mt][nt], ah[mt],
                             bb[nt >> 1][(nt & 1) * 2], bb[nt >> 1][(nt & 1) * 2 + 1]);
        }

        // issue chunk c+2 into stage (c+2)%3 (buffer freed by sync above)
        if (c + 2 < NC) {
            int stg2 = stg + 2; if (stg2 >= NSTG) stg2 -= NSTG;
            const uint32_t st2 = sb + (uint32_t)stg2 * STG_SZ;
            const int k2 = (c + 2) * KCH;
#pragma unroll
            for (int j = 0; j < 2; j++) {
                cp16(st2 + ST_A_H + sOff[j], gAh + k2 + j * 8);
                cp16(st2 + ST_A_L + sOff[j], gAl + k2 + j * 8);
                cp16(st2 + ST_B_H + sOff[j], gBh + k2 + j * 8);
                cp16(st2 + ST_B_L + sOff[j], gBl + k2 + j * 8);
            }
        }
        asm volatile("cp.async.commit_group;" ::: "memory");
        if (++stg == NSTG) stg = 0;
    }

    // ---- epilogue: direct fp32 stores; mode 1 fuses dt softplus/clip ----
    const int gid = lid >> 2, tig = lid & 3;
#pragma unroll
    for (int mt = 0; mt < 4; mt++) {
#pragma unroll
        for (int nt = 0; nt < 4; nt++) {
            int r0 = bm + wm * 64 + mt * 16 + gid;
            int c0 = bn + wn * 32 + nt * 8 + tig * 2;
            float v[4] = {acc[mt][nt][0], acc[mt][nt][1],
                          acc[mt][nt][2], acc[mt][nt][3]};
            if (mode == 1) {
                float bb0 = eb1[c0] + eb2[c0];
                float bb1 = eb1[c0 + 1] + eb2[c0 + 1];
#pragma unroll
                for (int i = 0; i < 4; i++) {
                    float t = v[i] + ((i & 1) ? bb1 : bb0);
                    float sp = (t > 20.f) ? t : log1pf(expf(t));
                    v[i] = fminf(fmaxf(sp, 0.f), 1.f);
                }
            }
            *(float2*)&C[(size_t)r0 * N + c0]       = make_float2(v[0], v[1]);
            *(float2*)&C[(size_t)(r0 + 8) * N + c0] = make_float2(v[2], v[3]);
        }
    }
}

// ---------------- fp32 -> (hi, lo) bf16 split ----------------
__global__ void split_kernel(const float* __restrict__ src,
                             __nv_bfloat16* __restrict__ hi,
                             __nv_bfloat16* __restrict__ lo, int n) {
    int i = blockIdx.x * 256 + threadIdx.x;
    if (i < n) {
        float v = src[i];
        __nv_bfloat16 h = __float2bfloat16(v);
        hi[i] = h;
        lo[i] = __float2bfloat16(v - __bfloat162float(h));
    }
}

// ---------------- embedding gather (+ split emit) ----------------
__global__ void embed_kernel(const int* __restrict__ ids,
                             const float* __restrict__ emb,
                             float* __restrict__ x,
                             __nv_bfloat16* __restrict__ xhi,
                             __nv_bfloat16* __restrict__ xlo) {
    int row = blockIdx.x;
    int id  = ids[row];
    float4 v = ((const float4*)(emb + (size_t)id * D_MODEL))[threadIdx.x];
    size_t base = (size_t)row * D_MODEL + threadIdx.x * 4;
    ((float4*)(x + (size_t)row * D_MODEL))[threadIdx.x] = v;
    float a[4] = {v.x, v.y, v.z, v.w};
#pragma unroll
    for (int j = 0; j < 4; j++) {
        __nv_bfloat16 h = __float2bfloat16(a[j]);
        xhi[base + j] = h;
        xlo[base + j] = __float2bfloat16(a[j] - __bfloat162float(h));
    }
}

// ---------------- skinny GEMM for B/C projections (N=16 each) ----------------
__global__ __launch_bounds__(256)
void bc_gemm(const float* __restrict__ x, const float* __restrict__ Wb,
             const float* __restrict__ Wc, float* __restrict__ Bm,
             float* __restrict__ Cm) {
    __shared__ float xs[8][D_MODEL];
    int row0 = blockIdx.x * 8;
    const float4* xg = (const float4*)(x + (size_t)row0 * D_MODEL);
    float4* xsv = (float4*)xs;
    for (int i = threadIdx.x; i < 8 * D_MODEL / 4; i += 256) xsv[i] = xg[i];
    __syncthreads();

    int r = threadIdx.x >> 5;
    int c = threadIdx.x & 31;
    const float* W = (c < 16) ? (Wb + (size_t)c * D_MODEL)
                              : (Wc + (size_t)(c - 16) * D_MODEL);
    const float4* Wv = (const float4*)W;
    const float4* xr = (const float4*)xs[r];
    float s = 0.f;
#pragma unroll 4
    for (int k = 0; k < D_MODEL / 4; k++) {
        float4 w = Wv[k], v = xr[k];
        s += w.x * v.x + w.y * v.y + w.z * v.z + w.w * v.w;
    }
    if (c < 16) Bm[(size_t)(row0 + r) * D_STATE + c]        = s;
    else        Cm[(size_t)(row0 + r) * D_STATE + (c - 16)] = s;
}

// ---------------- sequential SSM scan (2 threads/channel, 8 states each) ----------------
#define TCH 32
__global__ __launch_bounds__(128)
void ssm_scan(const float* __restrict__ xp, const float* __restrict__ dtc,
              const float* __restrict__ Bm, const float* __restrict__ Cm,
              const float* __restrict__ Amat, const float* __restrict__ Dvec,
              float* __restrict__ yout) {
    __shared__ float Bsh[TCH][D_STATE];
    __shared__ float Csh[TCH][D_STATE];

    const int wid = threadIdx.x >> 5, lid = threadIdx.x & 31;
    const int d    = blockIdx.x * 64 + wid * 16 + (lid & 15);
    const int half = lid >> 4;               // 0 or 1: states [0,8) or [8,16)
    const int b = blockIdx.y;

    float Ar[8], h[8];
#pragma unroll
    for (int j = 0; j < 8; j++) {
        Ar[j] = Amat[(size_t)d * D_STATE + half * 8 + j];
        h[j]  = 0.f;
    }
    const float Dd = Dvec[d];

    for (int tc = 0; tc < SEQ; tc += TCH) {
        ((float4*)Bsh)[threadIdx.x] =
            ((const float4*)(Bm + ((size_t)b * SEQ + tc) * D_STATE))[threadIdx.x];
        ((float4*)Csh)[threadIdx.x] =
            ((const float4*)(Cm + ((size_t)b * SEQ + tc) * D_STATE))[threadIdx.x];
        __syncthreads();

#pragma unroll 1
        for (int tt = 0; tt < TCH; tt++) {
            const size_t row = (size_t)b * SEQ + (tc + tt);
            float u  = xp [row * (2 * D_INNER) + d];
            float dv = dtc[row * D_INNER + d];
            float u01 = 0.1f * u;
            float adt = 0.1f * dv;
            float p0 = 0.f, p1 = 0.f;
#pragma unroll
            for (int j = 0; j < 8; j++) {
                int s = half * 8 + j;
                float hv = h[j];
                hv = fmaf(hv * Ar[j], adt, fmaf(Bsh[tt][s], u01, hv));
                h[j] = hv;
                float p = hv * Csh[tt][s];
                if (j & 1) p1 += p; else p0 += p;
            }
            float part = p0 + p1;
            float tot = part + __shfl_xor_sync(0xffffffffu, part, 16);
            if (!half) yout[row * D_INNER + d] = Dd * u + tot;
        }
        __syncthreads();
    }
}

// ---------------- gate multiply -> split bf16 y ----------------
__global__ void gate_mul(const float* __restrict__ y, const float* __restrict__ xp,
                         __nv_bfloat16* __restrict__ yhi,
                         __nv_bfloat16* __restrict__ ylo) {
    int i = blockIdx.x * 256 + threadIdx.x;     // NTOK*D_INNER
    int row = i / D_INNER;
    int d   = i - row * D_INNER;
    float g = xp[(size_t)row * (2 * D_INNER) + D_INNER + d];
    float v = y[i] * (1.f / (1.f + expf(-g)));
    __nv_bfloat16 h = __float2bfloat16(v);
    yhi[i] = h;
    ylo[i] = __float2bfloat16(v - __bfloat162float(h));
}

// ---------------- layernorm: out = post? + LN(in + res?) * g + b (+ split) ----------------
__device__ __forceinline__ float block_reduce(float v, float* red) {
    for (int o = 16; o > 0; o >>= 1) v += __shfl_down_sync(0xffffffffu, v, o);
    if ((threadIdx.x & 31) == 0) red[threadIdx.x >> 5] = v;
    __syncthreads();
    float t = 0.f;
#pragma unroll
    for (int w = 0; w < 8; w++) t += red[w];
    return t;
}

__global__ __launch_bounds__(256)
void ln_kernel(const float* __restrict__ in, const float* __restrict__ res,
               const float* __restrict__ post,
               const float* __restrict__ g, const float* __restrict__ b,
               float* __restrict__ out,
               __nv_bfloat16* __restrict__ ohi, __nv_bfloat16* __restrict__ olo) {
    __shared__ float red[8];
    const int row = blockIdx.x;
    const int t   = threadIdx.x;
    float v[3], pv[3];
    float s = 0.f;
#pragma unroll
    for (int i = 0; i < 3; i++) {
        int c = t + i * 256;
        float x = in[(size_t)row * D_MODEL + c];
        if (res) x += res[(size_t)row * D_MODEL + c];
        pv[i] = post ? post[(size_t)row * D_MODEL + c] : 0.f;
        v[i] = x;
        s += x;
    }
    float tot = block_reduce(s, red);
    float mu = tot * (1.f / D_MODEL);
    __syncthreads();
    float q = 0.f;
#pragma unroll
    for (int i = 0; i < 3; i++) {
        float dd = v[i] - mu;
        q += dd * dd;
    }
    float qtot = block_reduce(q, red);
    float rs = rsqrtf(qtot * (1.f / D_MODEL) + LN_EPS);
#pragma unroll
    for (int i = 0; i < 3; i++) {
        int c = t + i * 256;
        float o = pv[i] + (v[i] - mu) * rs * g[c] + b[c];
        size_t idx = (size_t)row * D_MODEL + c;
        out[idx] = o;
        if (ohi) {
            __nv_bfloat16 h = __float2bfloat16(o);
            ohi[idx] = h;
            olo[idx] = __float2bfloat16(o - __bfloat162float(h));
        }
    }
}

// ---------------- launch ----------------
extern "C" void kernel_launch(void* const* d_in, const int* in_sizes, int n_in,
                              void* d_out, int out_size) {
    const int*   input_ids = (const int*)  d_in[0];
    const float* emb       = (const float*)d_in[1];
    const float* W_in      = (const float*)d_in[2];   // [2, 3072, 768]
    const float* W_dt      = (const float*)d_in[3];   // [2, 1536, 768]
    const float* b_dt      = (const float*)d_in[4];
    const float* dt_bias   = (const float*)d_in[5];
    const float* W_B       = (const float*)d_in[6];
    const float* W_C       = (const float*)d_in[7];
    const float* Amat      = (const float*)d_in[8];
    const float* Dvec      = (const float*)d_in[9];
    const float* W_out     = (const float*)d_in[10];  // [2, 768, 1536]
    const float* ln_g      = (const float*)d_in[11];
    const float* ln_b      = (const float*)d_in[12];
    const float* fin_g     = (const float*)d_in[13];
    const float* fin_b     = (const float*)d_in[14];
    float* logits = (float*)d_out;                    // [4096, 32000]

    float *x, *xp, *dt, *Bm, *Cm, *y, *o;
    __nv_bfloat16 *xhi, *xlo, *yhi, *ylo, *ehi, *elo;
    __nv_bfloat16 *wihi, *wilo, *wdhi, *wdlo, *wohi, *wolo;
    cudaGetSymbolAddress((void**)&x,  g_x);
    cudaGetSymbolAddress((void**)&xp, g_xp);
    cudaGetSymbolAddress((void**)&dt, g_dt);
    cudaGetSymbolAddress((void**)&Bm, g_Bm);
    cudaGetSymbolAddress((void**)&Cm, g_Cm);
    cudaGetSymbolAddress((void**)&y,  g_y);
    cudaGetSymbolAddress((void**)&o,  g_o);
    cudaGetSymbolAddress((void**)&xhi, g_xhi);
    cudaGetSymbolAddress((void**)&xlo, g_xlo);
    cudaGetSymbolAddress((void**)&yhi, g_yhi);
    cudaGetSymbolAddress((void**)&ylo, g_ylo);
    cudaGetSymbolAddress((void**)&wihi, g_wihi);
    cudaGetSymbolAddress((void**)&wilo, g_wilo);
    cudaGetSymbolAddress((void**)&wdhi, g_wdhi);
    cudaGetSymbolAddress((void**)&wdlo, g_wdlo);
    cudaGetSymbolAddress((void**)&wohi, g_wohi);
    cudaGetSymbolAddress((void**)&wolo, g_wolo);
    cudaGetSymbolAddress((void**)&ehi, g_ehi);
    cudaGetSymbolAddress((void**)&elo, g_elo);

    cudaFuncSetAttribute(gemm_split, cudaFuncAttributeMaxDynamicSharedMemorySize,
                         GEMM_SMEM);

    // interleave splits with layer-0 gemms (puts gemm_split at early launch
    // indices so the ncu -s window lands on it)
    embed_kernel<<<NTOK, D_MODEL / 4>>>(input_ids, emb, x, xhi, xlo);   // 0
    {
        int n = N_LAYERS * 2 * D_INNER * D_MODEL;
        split_kernel<<<(n + 255) / 256, 256>>>(W_in, wihi, wilo, n);    // 1
    }
    gemm_split<<<dim3(NTOK / 128, 2 * D_INNER / 128), 256, GEMM_SMEM>>>(  // 2
        xhi, xlo, wihi, wilo, xp, NTOK, 2 * D_INNER, D_MODEL, 0, nullptr, nullptr);
    {
        int n = N_LAYERS * D_INNER * D_MODEL;
        split_kernel<<<(n + 255) / 256, 256>>>(W_dt, wdhi, wdlo, n);    // 3
    }
    gemm_split<<<dim3(NTOK / 128, D_INNER / 128), 256, GEMM_SMEM>>>(      // 4
        xhi, xlo, wdhi, wdlo, dt, NTOK, D_INNER, D_MODEL, 1, b_dt, dt_bias);
    {
        int n = N_LAYERS * D_MODEL * D_INNER;
        split_kernel<<<(n + 255) / 256, 256>>>(W_out, wohi, wolo, n);   // 5
        n = VOCAB * D_MODEL;
        split_kernel<<<(n + 255) / 256, 256>>>(emb, ehi, elo, n);       // 6
    }

    for (int l = 0; l < N_LAYERS; l++) {
        const size_t oWi = (size_t)l * 2 * D_INNER * D_MODEL;
        const size_t oWd = (size_t)l * D_INNER * D_MODEL;
        const size_t oWo = (size_t)l * D_MODEL * D_INNER;
        const float* bd = b_dt    + (size_t)l * D_INNER;
        const float* db = dt_bias + (size_t)l * D_INNER;
        const float* Wb = W_B   + (size_t)l * D_STATE * D_MODEL;
        const float* Wc = W_C   + (size_t)l * D_STATE * D_MODEL;
        const float* Al = Amat  + (size_t)l * D_INNER * D_STATE;
        const float* Dl = Dvec  + (size_t)l * D_INNER;
        const float* lg = ln_g  + (size_t)l * D_MODEL;
        const float* lb = ln_b  + (size_t)l * D_MODEL;

        if (l > 0) {
            // xp = x @ W_in^T, dt fused (layer 0 already launched above)
            gemm_split<<<dim3(NTOK / 128, 2 * D_INNER / 128), 256, GEMM_SMEM>>>(
                xhi, xlo, wihi + oWi, wilo + oWi, xp, NTOK, 2 * D_INNER, D_MODEL,
                0, nullptr, nullptr);
            gemm_split<<<dim3(NTOK / 128, D_INNER / 128), 256, GEMM_SMEM>>>(
                xhi, xlo, wdhi + oWd, wdlo + oWd, dt, NTOK, D_INNER, D_MODEL,
                1, bd, db);
        }
        bc_gemm<<<NTOK / 8, 256>>>(x, Wb, Wc, Bm, Cm);
        ssm_scan<<<dim3(D_INNER / 64, BATCH), 128>>>(xp, dt, Bm, Cm, Al, Dl, y);
        gate_mul<<<NTOK * D_INNER / 256, 256>>>(y, xp, yhi, ylo);
        // o = (y*gate) @ W_out^T : [4096, 768], K=1536
        gemm_split<<<dim3(NTOK / 128, D_MODEL / 128), 256, GEMM_SMEM>>>(
            yhi, ylo, wohi + oWo, wolo + oWo, o, NTOK, D_MODEL, D_INNER,
            0, nullptr, nullptr);
        // x <- x + LN(o + x)  (also emit split x for next GEMMs)
        ln_kernel<<<NTOK, 256>>>(o, x, x, lg, lb, x, xhi, xlo);
    }

    // final LN (emit split x for logits GEMM)
    ln_kernel<<<NTOK, 256>>>(x, nullptr, nullptr, fin_g, fin_b, x, xhi, xlo);
    // logits = x @ emb^T : [4096, 32000]
    gemm_split<<<dim3(NTOK / 128, VOCAB / 128), 256, GEMM_SMEM>>>(
        xhi, xlo, ehi, elo, logits, NTOK, VOCAB, D_MODEL,
        0, nullptr, nullptr);
}

// round 10
// speedup vs baseline: 1.1564x; 1.1564x over previous
#include <cuda_runtime.h>
#include <cuda_bf16.h>
#include <cuda_fp16.h>
#include <math.h>
#include <stdint.h>

// ---------------- problem constants ----------------
#define D_MODEL  768
#define N_LAYERS 2
#define D_STATE  16
#define VOCAB    32000
#define D_INNER  1536            // 2*D_MODEL
#define BATCH    2
#define SEQ      2048
#define NTOK     (BATCH*SEQ)     // 4096
#define LN_EPS   1e-5f

// ---------------- scratch (device globals; no mallocs allowed) ----------------
__device__ static float g_x [NTOK * D_MODEL];
__device__ static float g_xp[NTOK * 2 * D_INNER];
__device__ static float g_dt[NTOK * D_INNER];
__device__ static float g_Bm[NTOK * D_STATE];
__device__ static float g_Cm[NTOK * D_STATE];
__device__ static float g_y [NTOK * D_INNER];
__device__ static float g_o [NTOK * D_MODEL];
// bf16 split operands (layer GEMMs, 3-term)
__device__ static __nv_bfloat16 g_xhi[NTOK * D_MODEL];
__device__ static __nv_bfloat16 g_xlo[NTOK * D_MODEL];
__device__ static __nv_bfloat16 g_yhi[NTOK * D_INNER];
__device__ static __nv_bfloat16 g_ylo[NTOK * D_INNER];
__device__ static __nv_bfloat16 g_wihi[N_LAYERS * 2 * D_INNER * D_MODEL];
__device__ static __nv_bfloat16 g_wilo[N_LAYERS * 2 * D_INNER * D_MODEL];
__device__ static __nv_bfloat16 g_wdhi[N_LAYERS * D_INNER * D_MODEL];
__device__ static __nv_bfloat16 g_wdlo[N_LAYERS * D_INNER * D_MODEL];
__device__ static __nv_bfloat16 g_wohi[N_LAYERS * D_MODEL * D_INNER];
__device__ static __nv_bfloat16 g_wolo[N_LAYERS * D_MODEL * D_INNER];
// fp16 operands (logits GEMM, one-sided 2-term: x single, emb hi+lo)
__device__ static __half g_xf16[NTOK * D_MODEL];
__device__ static __half g_ehi [VOCAB * D_MODEL];
__device__ static __half g_elo [VOCAB * D_MODEL];

// ======================= helpers =======================
#define SW128X(o) ((o) ^ (((o) >> 3) & 0x70))

__device__ __forceinline__ uint32_t s2u(const void* p) {
    uint32_t a;
    asm("{ .reg .u64 t; cvta.to.shared.u64 t, %1; cvt.u32.u64 %0, t; }"
        : "=r"(a) : "l"(p));
    return a;
}

__device__ __forceinline__ void ldsm4(uint32_t* r, uint32_t addr) {
    asm volatile("ldmatrix.sync.aligned.m8n8.x4.shared.b16 {%0,%1,%2,%3}, [%4];"
                 : "=r"(r[0]), "=r"(r[1]), "=r"(r[2]), "=r"(r[3]) : "r"(addr));
}

__device__ __forceinline__ void mma_bf16(float* c, const uint32_t* a,
                                         uint32_t b0, uint32_t b1) {
    asm volatile(
        "mma.sync.aligned.m16n8k16.row.col.f32.bf16.bf16.f32 "
        "{%0,%1,%2,%3}, {%4,%5,%6,%7}, {%8,%9}, {%0,%1,%2,%3};"
        : "+f"(c[0]), "+f"(c[1]), "+f"(c[2]), "+f"(c[3])
        : "r"(a[0]), "r"(a[1]), "r"(a[2]), "r"(a[3]), "r"(b0), "r"(b1));
}

__device__ __forceinline__ void mma_fp16(float* c, const uint32_t* a,
                                         uint32_t b0, uint32_t b1) {
    asm volatile(
        "mma.sync.aligned.m16n8k16.row.col.f32.f16.f16.f32 "
        "{%0,%1,%2,%3}, {%4,%5,%6,%7}, {%8,%9}, {%0,%1,%2,%3};"
        : "+f"(c[0]), "+f"(c[1]), "+f"(c[2]), "+f"(c[3])
        : "r"(a[0]), "r"(a[1]), "r"(a[2]), "r"(a[3]), "r"(b0), "r"(b1));
}

__device__ __forceinline__ void cp16(uint32_t saddr, const void* gaddr) {
    asm volatile("cp.async.ca.shared.global [%0], [%1], 16;"
                 :: "r"(saddr), "l"(gaddr) : "memory");
}

// =================== split-bf16 tensor GEMM: C = A @ B^T (3-term) ===========
// Round-8 proven config: tile 128x128, K-chunk 64, single 64KB stage,
// 2 CTAs/SM (cross-CTA overlap hides latency; deeper pipelines measured slower
// twice). C = Ahi@Bhi + Ahi@Blo + Alo@Bhi, fp32 accum.
#define OPA_H 0
#define OPA_L 16384
#define OPB_H 32768
#define OPB_L 49152
#define GEMM_SMEM 65536

__global__ void __launch_bounds__(256, 2)
gemm_split(const __nv_bfloat16* __restrict__ Ahi, const __nv_bfloat16* __restrict__ Alo,
           const __nv_bfloat16* __restrict__ Bhi, const __nv_bfloat16* __restrict__ Blo,
           float* __restrict__ C, int M, int N, int K,
           int mode, const float* __restrict__ eb1, const float* __restrict__ eb2) {
    extern __shared__ char smc[];
    const uint32_t sb = s2u(smc);
    const int tid = threadIdx.x;
    const int wid = tid >> 5, lid = tid & 31;
    const int wm = wid & 1, wn = wid >> 1;          // warp grid 2(M) x 4(N)
    const int bm = blockIdx.x * 128, bn = blockIdx.y * 128;

    const int rin = lid & 7;
    const uint32_t xr = (uint32_t)rin << 4;
    const int amat = lid >> 3;
    const uint32_t aKq = (uint32_t)(amat >> 1) * 16;
    uint32_t aRow[4];
#pragma unroll
    for (int mt = 0; mt < 4; mt++)
        aRow[mt] = (uint32_t)(wm * 64 + mt * 16 + (amat & 1) * 8 + rin) * 128;
    const int bpair = lid >> 4, bsub = (lid >> 3) & 1;
    const uint32_t bKq = (uint32_t)bsub * 16;
    uint32_t bRow[2];
#pragma unroll
    for (int p = 0; p < 2; p++)
        bRow[p] = (uint32_t)(wn * 32 + p * 16 + bpair * 8 + rin) * 128;

    const int grow = tid >> 1;
    const int gch0 = (tid & 1) * 4;
    uint32_t sOff[4];
#pragma unroll
    for (int j = 0; j < 4; j++)
        sOff[j] = SW128X((uint32_t)grow * 128 + (uint32_t)(gch0 + j) * 16);

    const __nv_bfloat16* gAh = Ahi + (size_t)(bm + grow) * K + gch0 * 8;
    const __nv_bfloat16* gAl = Alo + (size_t)(bm + grow) * K + gch0 * 8;
    const __nv_bfloat16* gBh = Bhi + (size_t)(bn + grow) * K + gch0 * 8;
    const __nv_bfloat16* gBl = Blo + (size_t)(bn + grow) * K + gch0 * 8;

    float acc[4][4][4];
#pragma unroll
    for (int mt = 0; mt < 4; mt++)
#pragma unroll
        for (int nt = 0; nt < 4; nt++)
#pragma unroll
            for (int i = 0; i < 4; i++) acc[mt][nt][i] = 0.f;

    const int NC = K / 64;
    for (int c = 0; c < NC; c++) {
        const int k0 = c * 64;
        __syncthreads();
#pragma unroll
        for (int j = 0; j < 4; j++) {
            cp16(sb + OPA_H + sOff[j], gAh + k0 + j * 8);
            cp16(sb + OPA_L + sOff[j], gAl + k0 + j * 8);
            cp16(sb + OPB_H + sOff[j], gBh + k0 + j * 8);
            cp16(sb + OPB_L + sOff[j], gBl + k0 + j * 8);
        }
        asm volatile("cp.async.commit_group;" ::: "memory");
        asm volatile("cp.async.wait_group 0;" ::: "memory");
        __syncthreads();

#pragma unroll
        for (int ks = 0; ks < 4; ks++) {
            const uint32_t aoff = (((uint32_t)ks * 32 + aKq) ^ xr);
            const uint32_t boff = (((uint32_t)ks * 32 + bKq) ^ xr);
            uint32_t ah[4][4], bb[2][4];
#pragma unroll
            for (int mt = 0; mt < 4; mt++)
                ldsm4(ah[mt], sb + OPA_H + aRow[mt] + aoff);
#pragma unroll
            for (int p = 0; p < 2; p++)
                ldsm4(bb[p], sb + OPB_H + bRow[p] + boff);
#pragma unroll
            for (int mt = 0; mt < 4; mt++)
#pragma unroll
                for (int nt = 0; nt < 4; nt++)
                    mma_bf16(acc[mt][nt], ah[mt],
                             bb[nt >> 1][(nt & 1) * 2], bb[nt >> 1][(nt & 1) * 2 + 1]);
#pragma unroll
            for (int p = 0; p < 2; p++)
                ldsm4(bb[p], sb + OPB_L + bRow[p] + boff);
#pragma unroll
            for (int mt = 0; mt < 4; mt++)
#pragma unroll
                for (int nt = 0; nt < 4; nt++)
                    mma_bf16(acc[mt][nt], ah[mt],
                             bb[nt >> 1][(nt & 1) * 2], bb[nt >> 1][(nt & 1) * 2 + 1]);
#pragma unroll
            for (int mt = 0; mt < 4; mt++)
                ldsm4(ah[mt], sb + OPA_L + aRow[mt] + aoff);
#pragma unroll
            for (int p = 0; p < 2; p++)
                ldsm4(bb[p], sb + OPB_H + bRow[p] + boff);
#pragma unroll
            for (int mt = 0; mt < 4; mt++)
#pragma unroll
                for (int nt = 0; nt < 4; nt++)
                    mma_bf16(acc[mt][nt], ah[mt],
                             bb[nt >> 1][(nt & 1) * 2], bb[nt >> 1][(nt & 1) * 2 + 1]);
        }
    }

    const int gid = lid >> 2, tig = lid & 3;
#pragma unroll
    for (int mt = 0; mt < 4; mt++) {
#pragma unroll
        for (int nt = 0; nt < 4; nt++) {
            int r0 = bm + wm * 64 + mt * 16 + gid;
            int c0 = bn + wn * 32 + nt * 8 + tig * 2;
            float v[4] = {acc[mt][nt][0], acc[mt][nt][1],
                          acc[mt][nt][2], acc[mt][nt][3]};
            if (mode == 1) {
                float bb0 = eb1[c0] + eb2[c0];
                float bb1 = eb1[c0 + 1] + eb2[c0 + 1];
#pragma unroll
                for (int i = 0; i < 4; i++) {
                    float t = v[i] + ((i & 1) ? bb1 : bb0);
                    float sp = (t > 20.f) ? t : log1pf(expf(t));
                    v[i] = fminf(fmaxf(sp, 0.f), 1.f);
                }
            }
            *(float2*)&C[(size_t)r0 * N + c0]       = make_float2(v[0], v[1]);
            *(float2*)&C[(size_t)(r0 + 8) * N + c0] = make_float2(v[2], v[3]);
        }
    }
}

// ============ fp16 one-sided 2-term GEMM: C = A @ (Bhi+Blo)^T ==============
// A single fp16 (x), B split fp16 hi/lo (emb). 2 MMAs per k16 instead of 3.
// Used ONLY for the logits GEMM (output-final; no error compounding).
#define FP_A  0
#define FP_BH 16384
#define FP_BL 32768
#define GEMM16_SMEM 49152

__global__ void __launch_bounds__(256, 2)
gemm_fp16_2t(const __half* __restrict__ A,
             const __half* __restrict__ Bhi, const __half* __restrict__ Blo,
             float* __restrict__ C, int M, int N, int K) {
    extern __shared__ char smc[];
    const uint32_t sb = s2u(smc);
    const int tid = threadIdx.x;
    const int wid = tid >> 5, lid = tid & 31;
    const int wm = wid & 1, wn = wid >> 1;
    const int bm = blockIdx.x * 128, bn = blockIdx.y * 128;

    const int rin = lid & 7;
    const uint32_t xr = (uint32_t)rin << 4;
    const int amat = lid >> 3;
    const uint32_t aKq = (uint32_t)(amat >> 1) * 16;
    uint32_t aRow[4];
#pragma unroll
    for (int mt = 0; mt < 4; mt++)
        aRow[mt] = (uint32_t)(wm * 64 + mt * 16 + (amat & 1) * 8 + rin) * 128;
    const int bpair = lid >> 4, bsub = (lid >> 3) & 1;
    const uint32_t bKq = (uint32_t)bsub * 16;
    uint32_t bRow[2];
#pragma unroll
    for (int p = 0; p < 2; p++)
        bRow[p] = (uint32_t)(wn * 32 + p * 16 + bpair * 8 + rin) * 128;

    const int grow = tid >> 1;
    const int gch0 = (tid & 1) * 4;
    uint32_t sOff[4];
#pragma unroll
    for (int j = 0; j < 4; j++)
        sOff[j] = SW128X((uint32_t)grow * 128 + (uint32_t)(gch0 + j) * 16);

    const __half* gA  = A   + (size_t)(bm + grow) * K + gch0 * 8;
    const __half* gBh = Bhi + (size_t)(bn + grow) * K + gch0 * 8;
    const __half* gBl = Blo + (size_t)(bn + grow) * K + gch0 * 8;

    float acc[4][4][4];
#pragma unroll
    for (int mt = 0; mt < 4; mt++)
#pragma unroll
        for (int nt = 0; nt < 4; nt++)
#pragma unroll
            for (int i = 0; i < 4; i++) acc[mt][nt][i] = 0.f;

    const int NC = K / 64;
    for (int c = 0; c < NC; c++) {
        const int k0 = c * 64;
        __syncthreads();
#pragma unroll
        for (int j = 0; j < 4; j++) {
            cp16(sb + FP_A  + sOff[j], gA  + k0 + j * 8);
            cp16(sb + FP_BH + sOff[j], gBh + k0 + j * 8);
            cp16(sb + FP_BL + sOff[j], gBl + k0 + j * 8);
        }
        asm volatile("cp.async.commit_group;" ::: "memory");
        asm volatile("cp.async.wait_group 0;" ::: "memory");
        __syncthreads();

#pragma unroll
        for (int ks = 0; ks < 4; ks++) {
            const uint32_t aoff = (((uint32_t)ks * 32 + aKq) ^ xr);
            const uint32_t boff = (((uint32_t)ks * 32 + bKq) ^ xr);
            uint32_t ah[4][4], bb[2][4];
#pragma unroll
            for (int mt = 0; mt < 4; mt++)
                ldsm4(ah[mt], sb + FP_A + aRow[mt] + aoff);
            // combo 1: A x Bhi
#pragma unroll
            for (int p = 0; p < 2; p++)
                ldsm4(bb[p], sb + FP_BH + bRow[p] + boff);
#pragma unroll
            for (int mt = 0; mt < 4; mt++)
#pragma unroll
                for (int nt = 0; nt < 4; nt++)
                    mma_fp16(acc[mt][nt], ah[mt],
                             bb[nt >> 1][(nt & 1) * 2], bb[nt >> 1][(nt & 1) * 2 + 1]);
            // combo 2: A x Blo (reuse ah)
#pragma unroll
            for (int p = 0; p < 2; p++)
                ldsm4(bb[p], sb + FP_BL + bRow[p] + boff);
#pragma unroll
            for (int mt = 0; mt < 4; mt++)
#pragma unroll
                for (int nt = 0; nt < 4; nt++)
                    mma_fp16(acc[mt][nt], ah[mt],
                             bb[nt >> 1][(nt & 1) * 2], bb[nt >> 1][(nt & 1) * 2 + 1]);
        }
    }

    const int gid = lid >> 2, tig = lid & 3;
#pragma unroll
    for (int mt = 0; mt < 4; mt++) {
#pragma unroll
        for (int nt = 0; nt < 4; nt++) {
            int r0 = bm + wm * 64 + mt * 16 + gid;
            int c0 = bn + wn * 32 + nt * 8 + tig * 2;
            *(float2*)&C[(size_t)r0 * N + c0] =
                make_float2(acc[mt][nt][0], acc[mt][nt][1]);
            *(float2*)&C[(size_t)(r0 + 8) * N + c0] =
                make_float2(acc[mt][nt][2], acc[mt][nt][3]);
        }
    }
}

// ---------------- fp32 -> (hi, lo) bf16 split ----------------
__global__ void split_kernel(const float* __restrict__ src,
                             __nv_bfloat16* __restrict__ hi,
                             __nv_bfloat16* __restrict__ lo, int n) {
    int i = blockIdx.x * 256 + threadIdx.x;
    if (i < n) {
        float v = src[i];
        __nv_bfloat16 h = __float2bfloat16(v);
        hi[i] = h;
        lo[i] = __float2bfloat16(v - __bfloat162float(h));
    }
}

// ---------------- fp32 -> (hi, lo) fp16 split ----------------
__global__ void split_fp16_kernel(const float* __restrict__ src,
                                  __half* __restrict__ hi,
                                  __half* __restrict__ lo, int n) {
    int i = blockIdx.x * 256 + threadIdx.x;
    if (i < n) {
        float v = src[i];
        __half h = __float2half(v);
        hi[i] = h;
        lo[i] = __float2half(v - __half2float(h));
    }
}

// ---------------- embedding gather (+ bf16 split emit) ----------------
__global__ void embed_kernel(const int* __restrict__ ids,
                             const float* __restrict__ emb,
                             float* __restrict__ x,
                             __nv_bfloat16* __restrict__ xhi,
                             __nv_bfloat16* __restrict__ xlo) {
    int row = blockIdx.x;
    int id  = ids[row];
    float4 v = ((const float4*)(emb + (size_t)id * D_MODEL))[threadIdx.x];
    size_t base = (size_t)row * D_MODEL + threadIdx.x * 4;
    ((float4*)(x + (size_t)row * D_MODEL))[threadIdx.x] = v;
    float a[4] = {v.x, v.y, v.z, v.w};
#pragma unroll
    for (int j = 0; j < 4; j++) {
        __nv_bfloat16 h = __float2bfloat16(a[j]);
        xhi[base + j] = h;
        xlo[base + j] = __float2bfloat16(a[j] - __bfloat162float(h));
    }
}

// ---------------- skinny GEMM for B/C projections (N=16 each) ----------------
__global__ __launch_bounds__(256)
void bc_gemm(const float* __restrict__ x, const float* __restrict__ Wb,
             const float* __restrict__ Wc, float* __restrict__ Bm,
             float* __restrict__ Cm) {
    __shared__ float xs[8][D_MODEL];
    int row0 = blockIdx.x * 8;
    const float4* xg = (const float4*)(x + (size_t)row0 * D_MODEL);
    float4* xsv = (float4*)xs;
    for (int i = threadIdx.x; i < 8 * D_MODEL / 4; i += 256) xsv[i] = xg[i];
    __syncthreads();

    int r = threadIdx.x >> 5;
    int c = threadIdx.x & 31;
    const float* W = (c < 16) ? (Wb + (size_t)c * D_MODEL)
                              : (Wc + (size_t)(c - 16) * D_MODEL);
    const float4* Wv = (const float4*)W;
    const float4* xr = (const float4*)xs[r];
    float s = 0.f;
#pragma unroll 4
    for (int k = 0; k < D_MODEL / 4; k++) {
        float4 w = Wv[k], v = xr[k];
        s += w.x * v.x + w.y * v.y + w.z * v.z + w.w * v.w;
    }
    if (c < 16) Bm[(size_t)(row0 + r) * D_STATE + c]        = s;
    else        Cm[(size_t)(row0 + r) * D_STATE + (c - 16)] = s;
}

// ---------------- sequential SSM scan (2 threads/channel, 8 states each) ----------------
#define TCH 32
__global__ __launch_bounds__(128)
void ssm_scan(const float* __restrict__ xp, const float* __restrict__ dtc,
              const float* __restrict__ Bm, const float* __restrict__ Cm,
              const float* __restrict__ Amat, const float* __restrict__ Dvec,
              float* __restrict__ yout) {
    __shared__ float Bsh[TCH][D_STATE];
    __shared__ float Csh[TCH][D_STATE];

    const int wid = threadIdx.x >> 5, lid = threadIdx.x & 31;
    const int d    = blockIdx.x * 64 + wid * 16 + (lid & 15);
    const int half = lid >> 4;
    const int b = blockIdx.y;

    float Ar[8], h[8];
#pragma unroll
    for (int j = 0; j < 8; j++) {
        Ar[j] = Amat[(size_t)d * D_STATE + half * 8 + j];
        h[j]  = 0.f;
    }
    const float Dd = Dvec[d];

    for (int tc = 0; tc < SEQ; tc += TCH) {
        ((float4*)Bsh)[threadIdx.x] =
            ((const float4*)(Bm + ((size_t)b * SEQ + tc) * D_STATE))[threadIdx.x];
        ((float4*)Csh)[threadIdx.x] =
            ((const float4*)(Cm + ((size_t)b * SEQ + tc) * D_STATE))[threadIdx.x];
        __syncthreads();

#pragma unroll 1
        for (int tt = 0; tt < TCH; tt++) {
            const size_t row = (size_t)b * SEQ + (tc + tt);
            float u  = xp [row * (2 * D_INNER) + d];
            float dv = dtc[row * D_INNER + d];
            float u01 = 0.1f * u;
            float adt = 0.1f * dv;
            float p0 = 0.f, p1 = 0.f;
#pragma unroll
            for (int j = 0; j < 8; j++) {
                int s = half * 8 + j;
                float hv = h[j];
                hv = fmaf(hv * Ar[j], adt, fmaf(Bsh[tt][s], u01, hv));
                h[j] = hv;
                float p = hv * Csh[tt][s];
                if (j & 1) p1 += p; else p0 += p;
            }
            float part = p0 + p1;
            float tot = part + __shfl_xor_sync(0xffffffffu, part, 16);
            if (!half) yout[row * D_INNER + d] = Dd * u + tot;
        }
        __syncthreads();
    }
}

// ---------------- gate multiply -> split bf16 y ----------------
__global__ void gate_mul(const float* __restrict__ y, const float* __restrict__ xp,
                         __nv_bfloat16* __restrict__ yhi,
                         __nv_bfloat16* __restrict__ ylo) {
    int i = blockIdx.x * 256 + threadIdx.x;
    int row = i / D_INNER;
    int d   = i - row * D_INNER;
    float g = xp[(size_t)row * (2 * D_INNER) + D_INNER + d];
    float v = y[i] * (1.f / (1.f + expf(-g)));
    __nv_bfloat16 h = __float2bfloat16(v);
    yhi[i] = h;
    ylo[i] = __float2bfloat16(v - __bfloat162float(h));
}

// -------- layernorm: out = post? + LN(in + res?) * g + b (+ bf16/fp16 emit) --------
__device__ __forceinline__ float block_reduce(float v, float* red) {
    for (int o = 16; o > 0; o >>= 1) v += __shfl_down_sync(0xffffffffu, v, o);
    if ((threadIdx.x & 31) == 0) red[threadIdx.x >> 5] = v;
    __syncthreads();
    float t = 0.f;
#pragma unroll
    for (int w = 0; w < 8; w++) t += red[w];
    return t;
}

__global__ __launch_bounds__(256)
void ln_kernel(const float* __restrict__ in, const float* __restrict__ res,
               const float* __restrict__ post,
               const float* __restrict__ g, const float* __restrict__ b,
               float* __restrict__ out,
               __nv_bfloat16* __restrict__ ohi, __nv_bfloat16* __restrict__ olo,
               __half* __restrict__ of16) {
    __shared__ float red[8];
    const int row = blockIdx.x;
    const int t   = threadIdx.x;
    float v[3], pv[3];
    float s = 0.f;
#pragma unroll
    for (int i = 0; i < 3; i++) {
        int c = t + i * 256;
        float x = in[(size_t)row * D_MODEL + c];
        if (res) x += res[(size_t)row * D_MODEL + c];
        pv[i] = post ? post[(size_t)row * D_MODEL + c] : 0.f;
        v[i] = x;
        s += x;
    }
    float tot = block_reduce(s, red);
    float mu = tot * (1.f / D_MODEL);
    __syncthreads();
    float q = 0.f;
#pragma unroll
    for (int i = 0; i < 3; i++) {
        float dd = v[i] - mu;
        q += dd * dd;
    }
    float qtot = block_reduce(q, red);
    float rs = rsqrtf(qtot * (1.f / D_MODEL) + LN_EPS);
#pragma unroll
    for (int i = 0; i < 3; i++) {
        int c = t + i * 256;
        float o = pv[i] + (v[i] - mu) * rs * g[c] + b[c];
        size_t idx = (size_t)row * D_MODEL + c;
        out[idx] = o;
        if (ohi) {
            __nv_bfloat16 h = __float2bfloat16(o);
            ohi[idx] = h;
            olo[idx] = __float2bfloat16(o - __bfloat162float(h));
        }
        if (of16) of16[idx] = __float2half(o);
    }
}

// ---------------- launch ----------------
extern "C" void kernel_launch(void* const* d_in, const int* in_sizes, int n_in,
                              void* d_out, int out_size) {
    const int*   input_ids = (const int*)  d_in[0];
    const float* emb       = (const float*)d_in[1];
    const float* W_in      = (const float*)d_in[2];   // [2, 3072, 768]
    const float* W_dt      = (const float*)d_in[3];   // [2, 1536, 768]
    const float* b_dt      = (const float*)d_in[4];
    const float* dt_bias   = (const float*)d_in[5];
    const float* W_B       = (const float*)d_in[6];
    const float* W_C       = (const float*)d_in[7];
    const float* Amat      = (const float*)d_in[8];
    const float* Dvec      = (const float*)d_in[9];
    const float* W_out     = (const float*)d_in[10];  // [2, 768, 1536]
    const float* ln_g      = (const float*)d_in[11];
    const float* ln_b      = (const float*)d_in[12];
    const float* fin_g     = (const float*)d_in[13];
    const float* fin_b     = (const float*)d_in[14];
    float* logits = (float*)d_out;                    // [4096, 32000]

    float *x, *xp, *dt, *Bm, *Cm, *y, *o;
    __nv_bfloat16 *xhi, *xlo, *yhi, *ylo;
    __nv_bfloat16 *wihi, *wilo, *wdhi, *wdlo, *wohi, *wolo;
    __half *xf16, *ehi, *elo;
    cudaGetSymbolAddress((void**)&x,  g_x);
    cudaGetSymbolAddress((void**)&xp, g_xp);
    cudaGetSymbolAddress((void**)&dt, g_dt);
    cudaGetSymbolAddress((void**)&Bm, g_Bm);
    cudaGetSymbolAddress((void**)&Cm, g_Cm);
    cudaGetSymbolAddress((void**)&y,  g_y);
    cudaGetSymbolAddress((void**)&o,  g_o);
    cudaGetSymbolAddress((void**)&xhi, g_xhi);
    cudaGetSymbolAddress((void**)&xlo, g_xlo);
    cudaGetSymbolAddress((void**)&yhi, g_yhi);
    cudaGetSymbolAddress((void**)&ylo, g_ylo);
    cudaGetSymbolAddress((void**)&wihi, g_wihi);
    cudaGetSymbolAddress((void**)&wilo, g_wilo);
    cudaGetSymbolAddress((void**)&wdhi, g_wdhi);
    cudaGetSymbolAddress((void**)&wdlo, g_wdlo);
    cudaGetSymbolAddress((void**)&wohi, g_wohi);
    cudaGetSymbolAddress((void**)&wolo, g_wolo);
    cudaGetSymbolAddress((void**)&xf16, g_xf16);
    cudaGetSymbolAddress((void**)&ehi, g_ehi);
    cudaGetSymbolAddress((void**)&elo, g_elo);

    cudaFuncSetAttribute(gemm_split, cudaFuncAttributeMaxDynamicSharedMemorySize,
                         GEMM_SMEM);
    cudaFuncSetAttribute(gemm_fp16_2t, cudaFuncAttributeMaxDynamicSharedMemorySize,
                         GEMM16_SMEM);

    embed_kernel<<<NTOK, D_MODEL / 4>>>(input_ids, emb, x, xhi, xlo);

    // hoisted weight/emb splits (dedicated buffers; no serialization)
    {
        int n = N_LAYERS * 2 * D_INNER * D_MODEL;
        split_kernel<<<(n + 255) / 256, 256>>>(W_in, wihi, wilo, n);
        n = N_LAYERS * D_INNER * D_MODEL;
        split_kernel<<<(n + 255) / 256, 256>>>(W_dt, wdhi, wdlo, n);
        n = N_LAYERS * D_MODEL * D_INNER;
        split_kernel<<<(n + 255) / 256, 256>>>(W_out, wohi, wolo, n);
        n = VOCAB * D_MODEL;
        split_fp16_kernel<<<(n + 255) / 256, 256>>>(emb, ehi, elo, n);
    }

    for (int l = 0; l < N_LAYERS; l++) {
        const size_t oWi = (size_t)l * 2 * D_INNER * D_MODEL;
        const size_t oWd = (size_t)l * D_INNER * D_MODEL;
        const size_t oWo = (size_t)l * D_MODEL * D_INNER;
        const float* bd = b_dt    + (size_t)l * D_INNER;
        const float* db = dt_bias + (size_t)l * D_INNER;
        const float* Wb = W_B   + (size_t)l * D_STATE * D_MODEL;
        const float* Wc = W_C   + (size_t)l * D_STATE * D_MODEL;
        const float* Al = Amat  + (size_t)l * D_INNER * D_STATE;
        const float* Dl = Dvec  + (size_t)l * D_INNER;
        const float* lg = ln_g  + (size_t)l * D_MODEL;
        const float* lb = ln_b  + (size_t)l * D_MODEL;

        // xp = x @ W_in^T : [4096, 3072]
        gemm_split<<<dim3(NTOK / 128, 2 * D_INNER / 128), 256, GEMM_SMEM>>>(
            xhi, xlo, wihi + oWi, wilo + oWi, xp, NTOK, 2 * D_INNER, D_MODEL,
            0, nullptr, nullptr);
        // dt = softplus/clip(x @ W_dt^T + biases) fused in epilogue
        gemm_split<<<dim3(NTOK / 128, D_INNER / 128), 256, GEMM_SMEM>>>(
            xhi, xlo, wdhi + oWd, wdlo + oWd, dt, NTOK, D_INNER, D_MODEL,
            1, bd, db);
        bc_gemm<<<NTOK / 8, 256>>>(x, Wb, Wc, Bm, Cm);
        ssm_scan<<<dim3(D_INNER / 64, BATCH), 128>>>(xp, dt, Bm, Cm, Al, Dl, y);
        gate_mul<<<NTOK * D_INNER / 256, 256>>>(y, xp, yhi, ylo);
        // o = (y*gate) @ W_out^T : [4096, 768], K=1536
        gemm_split<<<dim3(NTOK / 128, D_MODEL / 128), 256, GEMM_SMEM>>>(
            yhi, ylo, wohi + oWo, wolo + oWo, o, NTOK, D_MODEL, D_INNER,
            0, nullptr, nullptr);
        // x <- x + LN(o + x)  (emit bf16 split x for next layer's GEMMs)
        ln_kernel<<<NTOK, 256>>>(o, x, x, lg, lb, x, xhi, xlo, nullptr);
    }

    // final LN (emit fp16 x for logits GEMM)
    ln_kernel<<<NTOK, 256>>>(x, nullptr, nullptr, fin_g, fin_b, x,
                             nullptr, nullptr, xf16);
    // logits = x @ emb^T : [4096, 32000]  (fp16 one-sided 2-term)
    gemm_fp16_2t<<<dim3(NTOK / 128, VOCAB / 128), 256, GEMM16_SMEM>>>(
        xf16, ehi, elo, logits, NTOK, VOCAB, D_MODEL);
}

// round 11
// speedup vs baseline: 1.9975x; 1.7274x over previous
#include <cuda_runtime.h>
#include <cuda_bf16.h>
#include <cuda_fp16.h>
#include <math.h>
#include <stdint.h>

// ---------------- problem constants ----------------
#define D_MODEL  768
#define N_LAYERS 2
#define D_STATE  16
#define VOCAB    32000
#define D_INNER  1536            // 2*D_MODEL
#define BATCH    2
#define SEQ      2048
#define NTOK     (BATCH*SEQ)     // 4096
#define LN_EPS   1e-5f

// ---------------- scratch (device globals; no mallocs allowed) ----------------
__device__ static float g_x [NTOK * D_MODEL];
__device__ static float g_xp[NTOK * 2 * D_INNER];
__device__ static float g_dt[NTOK * D_INNER];
__device__ static float g_Bm[NTOK * D_STATE];
__device__ static float g_Cm[NTOK * D_STATE];
__device__ static float g_y [NTOK * D_INNER];
__device__ static float g_o [NTOK * D_MODEL];
// bf16 split operands (layer GEMMs, 3-term)
__device__ static __nv_bfloat16 g_xhi[NTOK * D_MODEL];
__device__ static __nv_bfloat16 g_xlo[NTOK * D_MODEL];
__device__ static __nv_bfloat16 g_yhi[NTOK * D_INNER];
__device__ static __nv_bfloat16 g_ylo[NTOK * D_INNER];
__device__ static __nv_bfloat16 g_wihi[N_LAYERS * 2 * D_INNER * D_MODEL];
__device__ static __nv_bfloat16 g_wilo[N_LAYERS * 2 * D_INNER * D_MODEL];
__device__ static __nv_bfloat16 g_wdhi[N_LAYERS * D_INNER * D_MODEL];
__device__ static __nv_bfloat16 g_wdlo[N_LAYERS * D_INNER * D_MODEL];
__device__ static __nv_bfloat16 g_wohi[N_LAYERS * D_MODEL * D_INNER];
__device__ static __nv_bfloat16 g_wolo[N_LAYERS * D_MODEL * D_INNER];
// fp16 operands (logits GEMM, one-sided 2-term: x single, emb hi+lo)
__device__ static __half g_xf16[NTOK * D_MODEL];
__device__ static __half g_ehi [VOCAB * D_MODEL];
__device__ static __half g_elo [VOCAB * D_MODEL];

// ======================= helpers =======================
#define SW128X(o) ((o) ^ (((o) >> 3) & 0x70))

__device__ __forceinline__ uint32_t s2u(const void* p) {
    uint32_t a;
    asm("{ .reg .u64 t; cvta.to.shared.u64 t, %1; cvt.u32.u64 %0, t; }"
        : "=r"(a) : "l"(p));
    return a;
}

__device__ __forceinline__ void ldsm4(uint32_t* r, uint32_t addr) {
    asm volatile("ldmatrix.sync.aligned.m8n8.x4.shared.b16 {%0,%1,%2,%3}, [%4];"
                 : "=r"(r[0]), "=r"(r[1]), "=r"(r[2]), "=r"(r[3]) : "r"(addr));
}

__device__ __forceinline__ void mma_bf16(float* c, const uint32_t* a,
                                         uint32_t b0, uint32_t b1) {
    asm volatile(
        "mma.sync.aligned.m16n8k16.row.col.f32.bf16.bf16.f32 "
        "{%0,%1,%2,%3}, {%4,%5,%6,%7}, {%8,%9}, {%0,%1,%2,%3};"
        : "+f"(c[0]), "+f"(c[1]), "+f"(c[2]), "+f"(c[3])
        : "r"(a[0]), "r"(a[1]), "r"(a[2]), "r"(a[3]), "r"(b0), "r"(b1));
}

__device__ __forceinline__ void mma_fp16(float* c, const uint32_t* a,
                                         uint32_t b0, uint32_t b1) {
    asm volatile(
        "mma.sync.aligned.m16n8k16.row.col.f32.f16.f16.f32 "
        "{%0,%1,%2,%3}, {%4,%5,%6,%7}, {%8,%9}, {%0,%1,%2,%3};"
        : "+f"(c[0]), "+f"(c[1]), "+f"(c[2]), "+f"(c[3])
        : "r"(a[0]), "r"(a[1]), "r"(a[2]), "r"(a[3]), "r"(b0), "r"(b1));
}

__device__ __forceinline__ void cp16(uint32_t saddr, const void* gaddr) {
    asm volatile("cp.async.ca.shared.global [%0], [%1], 16;"
                 :: "r"(saddr), "l"(gaddr) : "memory");
}

__device__ __forceinline__ uint32_t pack_bf2(float a, float b) {
    __nv_bfloat162 t = __floats2bfloat162_rn(a, b);
    return *(uint32_t*)&t;
}
__device__ __forceinline__ uint32_t pack_hf2(float a, float b) {
    __half2 t = __floats2half2_rn(a, b);
    return *(uint32_t*)&t;
}

// =================== split-bf16 tensor GEMM: C = A @ B^T (3-term) ===========
// Round-8 proven config: tile 128x128, K-chunk 64, single 64KB stage,
// 2 CTAs/SM (cross-CTA overlap hides latency; deeper pipelines measured slower
// twice). C = Ahi@Bhi + Ahi@Blo + Alo@Bhi, fp32 accum.
#define OPA_H 0
#define OPA_L 16384
#define OPB_H 32768
#define OPB_L 49152
#define GEMM_SMEM 65536

__global__ void __launch_bounds__(256, 2)
gemm_split(const __nv_bfloat16* __restrict__ Ahi, const __nv_bfloat16* __restrict__ Alo,
           const __nv_bfloat16* __restrict__ Bhi, const __nv_bfloat16* __restrict__ Blo,
           float* __restrict__ C, int M, int N, int K,
           int mode, const float* __restrict__ eb1, const float* __restrict__ eb2) {
    extern __shared__ char smc[];
    const uint32_t sb = s2u(smc);
    const int tid = threadIdx.x;
    const int wid = tid >> 5, lid = tid & 31;
    const int wm = wid & 1, wn = wid >> 1;          // warp grid 2(M) x 4(N)
    const int bm = blockIdx.x * 128, bn = blockIdx.y * 128;

    const int rin = lid & 7;
    const uint32_t xr = (uint32_t)rin << 4;
    const int amat = lid >> 3;
    const uint32_t aKq = (uint32_t)(amat >> 1) * 16;
    uint32_t aRow[4];
#pragma unroll
    for (int mt = 0; mt < 4; mt++)
        aRow[mt] = (uint32_t)(wm * 64 + mt * 16 + (amat & 1) * 8 + rin) * 128;
    const int bpair = lid >> 4, bsub = (lid >> 3) & 1;
    const uint32_t bKq = (uint32_t)bsub * 16;
    uint32_t bRow[2];
#pragma unroll
    for (int p = 0; p < 2; p++)
        bRow[p] = (uint32_t)(wn * 32 + p * 16 + bpair * 8 + rin) * 128;

    const int grow = tid >> 1;
    const int gch0 = (tid & 1) * 4;
    uint32_t sOff[4];
#pragma unroll
    for (int j = 0; j < 4; j++)
        sOff[j] = SW128X((uint32_t)grow * 128 + (uint32_t)(gch0 + j) * 16);

    const __nv_bfloat16* gAh = Ahi + (size_t)(bm + grow) * K + gch0 * 8;
    const __nv_bfloat16* gAl = Alo + (size_t)(bm + grow) * K + gch0 * 8;
    const __nv_bfloat16* gBh = Bhi + (size_t)(bn + grow) * K + gch0 * 8;
    const __nv_bfloat16* gBl = Blo + (size_t)(bn + grow) * K + gch0 * 8;

    float acc[4][4][4];
#pragma unroll
    for (int mt = 0; mt < 4; mt++)
#pragma unroll
        for (int nt = 0; nt < 4; nt++)
#pragma unroll
            for (int i = 0; i < 4; i++) acc[mt][nt][i] = 0.f;

    const int NC = K / 64;
    for (int c = 0; c < NC; c++) {
        const int k0 = c * 64;
        __syncthreads();
#pragma unroll
        for (int j = 0; j < 4; j++) {
            cp16(sb + OPA_H + sOff[j], gAh + k0 + j * 8);
            cp16(sb + OPA_L + sOff[j], gAl + k0 + j * 8);
            cp16(sb + OPB_H + sOff[j], gBh + k0 + j * 8);
            cp16(sb + OPB_L + sOff[j], gBl + k0 + j * 8);
        }
        asm volatile("cp.async.commit_group;" ::: "memory");
        asm volatile("cp.async.wait_group 0;" ::: "memory");
        __syncthreads();

#pragma unroll
        for (int ks = 0; ks < 4; ks++) {
            const uint32_t aoff = (((uint32_t)ks * 32 + aKq) ^ xr);
            const uint32_t boff = (((uint32_t)ks * 32 + bKq) ^ xr);
            uint32_t ah[4][4], bb[2][4];
#pragma unroll
            for (int mt = 0; mt < 4; mt++)
                ldsm4(ah[mt], sb + OPA_H + aRow[mt] + aoff);
#pragma unroll
            for (int p = 0; p < 2; p++)
                ldsm4(bb[p], sb + OPB_H + bRow[p] + boff);
#pragma unroll
            for (int mt = 0; mt < 4; mt++)
#pragma unroll
                for (int nt = 0; nt < 4; nt++)
                    mma_bf16(acc[mt][nt], ah[mt],
                             bb[nt >> 1][(nt & 1) * 2], bb[nt >> 1][(nt & 1) * 2 + 1]);
#pragma unroll
            for (int p = 0; p < 2; p++)
                ldsm4(bb[p], sb + OPB_L + bRow[p] + boff);
#pragma unroll
            for (int mt = 0; mt < 4; mt++)
#pragma unroll
                for (int nt = 0; nt < 4; nt++)
                    mma_bf16(acc[mt][nt], ah[mt],
                             bb[nt >> 1][(nt & 1) * 2], bb[nt >> 1][(nt & 1) * 2 + 1]);
#pragma unroll
            for (int mt = 0; mt < 4; mt++)
                ldsm4(ah[mt], sb + OPA_L + aRow[mt] + aoff);
#pragma unroll
            for (int p = 0; p < 2; p++)
                ldsm4(bb[p], sb + OPB_H + bRow[p] + boff);
#pragma unroll
            for (int mt = 0; mt < 4; mt++)
#pragma unroll
                for (int nt = 0; nt < 4; nt++)
                    mma_bf16(acc[mt][nt], ah[mt],
                             bb[nt >> 1][(nt & 1) * 2], bb[nt >> 1][(nt & 1) * 2 + 1]);
        }
    }

    const int gid = lid >> 2, tig = lid & 3;
#pragma unroll
    for (int mt = 0; mt < 4; mt++) {
#pragma unroll
        for (int nt = 0; nt < 4; nt++) {
            int r0 = bm + wm * 64 + mt * 16 + gid;
            int c0 = bn + wn * 32 + nt * 8 + tig * 2;
            float v[4] = {acc[mt][nt][0], acc[mt][nt][1],
                          acc[mt][nt][2], acc[mt][nt][3]};
            if (mode == 1) {
                float bb0 = eb1[c0] + eb2[c0];
                float bb1 = eb1[c0 + 1] + eb2[c0 + 1];
#pragma unroll
                for (int i = 0; i < 4; i++) {
                    float t = v[i] + ((i & 1) ? bb1 : bb0);
                    float sp = (t > 20.f) ? t : log1pf(expf(t));
                    v[i] = fminf(fmaxf(sp, 0.f), 1.f);
                }
            }
            *(float2*)&C[(size_t)r0 * N + c0]       = make_float2(v[0], v[1]);
            *(float2*)&C[(size_t)(r0 + 8) * N + c0] = make_float2(v[2], v[3]);
        }
    }
}

// ============ fp16 one-sided 2-term GEMM: C = A @ (Bhi+Blo)^T ==============
// A single fp16 (x), B split fp16 hi/lo (emb). Logits GEMM only (output-final).
#define FP_A  0
#define FP_BH 16384
#define FP_BL 32768
#define GEMM16_SMEM 49152

__global__ void __launch_bounds__(256, 2)
gemm_fp16_2t(const __half* __restrict__ A,
             const __half* __restrict__ Bhi, const __half* __restrict__ Blo,
             float* __restrict__ C, int M, int N, int K) {
    extern __shared__ char smc[];
    const uint32_t sb = s2u(smc);
    const int tid = threadIdx.x;
    const int wid = tid >> 5, lid = tid & 31;
    const int wm = wid & 1, wn = wid >> 1;
    const int bm = blockIdx.x * 128, bn = blockIdx.y * 128;

    const int rin = lid & 7;
    const uint32_t xr = (uint32_t)rin << 4;
    const int amat = lid >> 3;
    const uint32_t aKq = (uint32_t)(amat >> 1) * 16;
    uint32_t aRow[4];
#pragma unroll
    for (int mt = 0; mt < 4; mt++)
        aRow[mt] = (uint32_t)(wm * 64 + mt * 16 + (amat & 1) * 8 + rin) * 128;
    const int bpair = lid >> 4, bsub = (lid >> 3) & 1;
    const uint32_t bKq = (uint32_t)bsub * 16;
    uint32_t bRow[2];
#pragma unroll
    for (int p = 0; p < 2; p++)
        bRow[p] = (uint32_t)(wn * 32 + p * 16 + bpair * 8 + rin) * 128;

    const int grow = tid >> 1;
    const int gch0 = (tid & 1) * 4;
    uint32_t sOff[4];
#pragma unroll
    for (int j = 0; j < 4; j++)
        sOff[j] = SW128X((uint32_t)grow * 128 + (uint32_t)(gch0 + j) * 16);

    const __half* gA  = A   + (size_t)(bm + grow) * K + gch0 * 8;
    const __half* gBh = Bhi + (size_t)(bn + grow) * K + gch0 * 8;
    const __half* gBl = Blo + (size_t)(bn + grow) * K + gch0 * 8;

    float acc[4][4][4];
#pragma unroll
    for (int mt = 0; mt < 4; mt++)
#pragma unroll
        for (int nt = 0; nt < 4; nt++)
#pragma unroll
            for (int i = 0; i < 4; i++) acc[mt][nt][i] = 0.f;

    const int NC = K / 64;
    for (int c = 0; c < NC; c++) {
        const int k0 = c * 64;
        __syncthreads();
#pragma unroll
        for (int j = 0; j < 4; j++) {
            cp16(sb + FP_A  + sOff[j], gA  + k0 + j * 8);
            cp16(sb + FP_BH + sOff[j], gBh + k0 + j * 8);
            cp16(sb + FP_BL + sOff[j], gBl + k0 + j * 8);
        }
        asm volatile("cp.async.commit_group;" ::: "memory");
        asm volatile("cp.async.wait_group 0;" ::: "memory");
        __syncthreads();

#pragma unroll
        for (int ks = 0; ks < 4; ks++) {
            const uint32_t aoff = (((uint32_t)ks * 32 + aKq) ^ xr);
            const uint32_t boff = (((uint32_t)ks * 32 + bKq) ^ xr);
            uint32_t ah[4][4], bb[2][4];
#pragma unroll
            for (int mt = 0; mt < 4; mt++)
                ldsm4(ah[mt], sb + FP_A + aRow[mt] + aoff);
#pragma unroll
            for (int p = 0; p < 2; p++)
                ldsm4(bb[p], sb + FP_BH + bRow[p] + boff);
#pragma unroll
            for (int mt = 0; mt < 4; mt++)
#pragma unroll
                for (int nt = 0; nt < 4; nt++)
                    mma_fp16(acc[mt][nt], ah[mt],
                             bb[nt >> 1][(nt & 1) * 2], bb[nt >> 1][(nt & 1) * 2 + 1]);
#pragma unroll
            for (int p = 0; p < 2; p++)
                ldsm4(bb[p], sb + FP_BL + bRow[p] + boff);
#pragma unroll
            for (int mt = 0; mt < 4; mt++)
#pragma unroll
                for (int nt = 0; nt < 4; nt++)
                    mma_fp16(acc[mt][nt], ah[mt],
                             bb[nt >> 1][(nt & 1) * 2], bb[nt >> 1][(nt & 1) * 2 + 1]);
        }
    }

    const int gid = lid >> 2, tig = lid & 3;
#pragma unroll
    for (int mt = 0; mt < 4; mt++) {
#pragma unroll
        for (int nt = 0; nt < 4; nt++) {
            int r0 = bm + wm * 64 + mt * 16 + gid;
            int c0 = bn + wn * 32 + nt * 8 + tig * 2;
            *(float2*)&C[(size_t)r0 * N + c0] =
                make_float2(acc[mt][nt][0], acc[mt][nt][1]);
            *(float2*)&C[(size_t)(r0 + 8) * N + c0] =
                make_float2(acc[mt][nt][2], acc[mt][nt][3]);
        }
    }
}

// ------------- vectorized fp32 -> (hi, lo) bf16 split (4 elems/thread) -------------
__global__ void split_kernel(const float* __restrict__ src,
                             __nv_bfloat16* __restrict__ hi,
                             __nv_bfloat16* __restrict__ lo, int n4) {
    int i = blockIdx.x * 256 + threadIdx.x;
    if (i < n4) {
        float4 v = ((const float4*)src)[i];
        float a[4] = {v.x, v.y, v.z, v.w};
        float hf[4], lf[4];
#pragma unroll
        for (int j = 0; j < 4; j++) {
            __nv_bfloat16 h = __float2bfloat16(a[j]);
            hf[j] = __bfloat162float(h);
            lf[j] = a[j] - hf[j];
        }
        uint2 hv = make_uint2(pack_bf2(hf[0], hf[1]), pack_bf2(hf[2], hf[3]));
        uint2 lv = make_uint2(pack_bf2(lf[0], lf[1]), pack_bf2(lf[2], lf[3]));
        ((uint2*)hi)[i] = hv;
        ((uint2*)lo)[i] = lv;
    }
}

// ------------- vectorized fp32 -> (hi, lo) fp16 split ----------------
__global__ void split_fp16_kernel(const float* __restrict__ src,
                                  __half* __restrict__ hi,
                                  __half* __restrict__ lo, int n4) {
    int i = blockIdx.x * 256 + threadIdx.x;
    if (i < n4) {
        float4 v = ((const float4*)src)[i];
        float a[4] = {v.x, v.y, v.z, v.w};
        float hf[4], lf[4];
#pragma unroll
        for (int j = 0; j < 4; j++) {
            __half h = __float2half(a[j]);
            hf[j] = __half2float(h);
            lf[j] = a[j] - hf[j];
        }
        uint2 hv = make_uint2(pack_hf2(hf[0], hf[1]), pack_hf2(hf[2], hf[3]));
        uint2 lv = make_uint2(pack_hf2(lf[0], lf[1]), pack_hf2(lf[2], lf[3]));
        ((uint2*)hi)[i] = hv;
        ((uint2*)lo)[i] = lv;
    }
}

// ---------------- embedding gather (+ bf16 split emit) ----------------
__global__ void embed_kernel(const int* __restrict__ ids,
                             const float* __restrict__ emb,
                             float* __restrict__ x,
                             __nv_bfloat16* __restrict__ xhi,
                             __nv_bfloat16* __restrict__ xlo) {
    int row = blockIdx.x;
    int id  = ids[row];
    float4 v = ((const float4*)(emb + (size_t)id * D_MODEL))[threadIdx.x];
    size_t base = (size_t)row * D_MODEL + threadIdx.x * 4;
    ((float4*)(x + (size_t)row * D_MODEL))[threadIdx.x] = v;
    float a[4] = {v.x, v.y, v.z, v.w};
#pragma unroll
    for (int j = 0; j < 4; j++) {
        __nv_bfloat16 h = __float2bfloat16(a[j]);
        xhi[base + j] = h;
        xlo[base + j] = __float2bfloat16(a[j] - __bfloat162float(h));
    }
}

// ---------------- skinny GEMM for B/C projections (N=16 each) ----------------
__global__ __launch_bounds__(256)
void bc_gemm(const float* __restrict__ x, const float* __restrict__ Wb,
             const float* __restrict__ Wc, float* __restrict__ Bm,
             float* __restrict__ Cm) {
    __shared__ float xs[8][D_MODEL];
    int row0 = blockIdx.x * 8;
    const float4* xg = (const float4*)(x + (size_t)row0 * D_MODEL);
    float4* xsv = (float4*)xs;
    for (int i = threadIdx.x; i < 8 * D_MODEL / 4; i += 256) xsv[i] = xg[i];
    __syncthreads();

    int r = threadIdx.x >> 5;
    int c = threadIdx.x & 31;
    const float* W = (c < 16) ? (Wb + (size_t)c * D_MODEL)
                              : (Wc + (size_t)(c - 16) * D_MODEL);
    const float4* Wv = (const float4*)W;
    const float4* xr = (const float4*)xs[r];
    float s = 0.f;
#pragma unroll 4
    for (int k = 0; k < D_MODEL / 4; k++) {
        float4 w = Wv[k], v = xr[k];
        s += w.x * v.x + w.y * v.y + w.z * v.z + w.w * v.w;
    }
    if (c < 16) Bm[(size_t)(row0 + r) * D_STATE + c]        = s;
    else        Cm[(size_t)(row0 + r) * D_STATE + (c - 16)] = s;
}

// ======== sequential SSM scan: cp.async double-buffered chunk staging ========
// Block: 128 threads = 64 channels x 2 state-halves; grid (D_INNER/64, BATCH).
// Per 32-step chunk, prefetch xp/dt/B/C slabs into SMEM while computing the
// previous chunk; inner loop is pure SMEM + register FMA (8-state ILP hides
// the 2-FMA recurrence chain).
#define TCH 32
__global__ __launch_bounds__(128)
void ssm_scan(const float* __restrict__ xp, const float* __restrict__ dtc,
              const float* __restrict__ Bm, const float* __restrict__ Cm,
              const float* __restrict__ Amat, const float* __restrict__ Dvec,
              float* __restrict__ yout) {
    __shared__ float  xp_s[2][TCH][64];
    __shared__ float  dt_s[2][TCH][64];
    __shared__ float4 B_s [2][TCH][4];
    __shared__ float4 C_s [2][TCH][4];

    const int tid = threadIdx.x;
    const int wid = tid >> 5, lid = tid & 31;
    const int ch   = wid * 16 + (lid & 15);      // 0..63 local channel
    const int half = lid >> 4;                   // states [0,8) or [8,16)
    const int d0 = blockIdx.x * 64;
    const int d  = d0 + ch;
    const int b  = blockIdx.y;

    float Ar[8], h[8];
#pragma unroll
    for (int j = 0; j < 8; j++) {
        Ar[j] = Amat[(size_t)d * D_STATE + half * 8 + j];
        h[j]  = 0.f;
    }
    const float Dd = Dvec[d];

    const int tt0 = tid >> 4;            // 0..7
    const int seg = (tid & 15) * 4;      // float offset within 64-ch row

    auto issue_chunk = [&](int buf, int tc) {
#pragma unroll
        for (int r = 0; r < 4; r++) {
            int tt = tt0 + r * 8;
            size_t row = (size_t)b * SEQ + tc + tt;
            cp16(s2u(&xp_s[buf][tt][seg]), xp  + row * (2 * D_INNER) + d0 + seg);
            cp16(s2u(&dt_s[buf][tt][seg]), dtc + row * D_INNER       + d0 + seg);
        }
        size_t bcbase = ((size_t)b * SEQ + tc) * D_STATE;   // 512 floats / chunk
        cp16(s2u((float*)B_s[buf] + tid * 4), Bm + bcbase + tid * 4);
        cp16(s2u((float*)C_s[buf] + tid * 4), Cm + bcbase + tid * 4);
        asm volatile("cp.async.commit_group;" ::: "memory");
    };

    issue_chunk(0, 0);
    const int NCH = SEQ / TCH;
    for (int c = 0; c < NCH; c++) {
        const int buf = c & 1;
        if (c + 1 < NCH) {
            issue_chunk(buf ^ 1, (c + 1) * TCH);
            asm volatile("cp.async.wait_group 1;" ::: "memory");
        } else {
            asm volatile("cp.async.wait_group 0;" ::: "memory");
        }
        __syncthreads();

        const int tcg = c * TCH;
#pragma unroll 4
        for (int tt = 0; tt < TCH; tt++) {
            float u  = xp_s[buf][tt][ch];
            float dv = dt_s[buf][tt][ch];
            float4 Bv0 = B_s[buf][tt][half * 2];
            float4 Bv1 = B_s[buf][tt][half * 2 + 1];
            float4 Cv0 = C_s[buf][tt][half * 2];
            float4 Cv1 = C_s[buf][tt][half * 2 + 1];
            float bs[8] = {Bv0.x, Bv0.y, Bv0.z, Bv0.w, Bv1.x, Bv1.y, Bv1.z, Bv1.w};
            float cs[8] = {Cv0.x, Cv0.y, Cv0.z, Cv0.w, Cv1.x, Cv1.y, Cv1.z, Cv1.w};
            float u01 = 0.1f * u;
            float adt = 0.1f * dv;
            float p0 = 0.f, p1 = 0.f;
#pragma unroll
            for (int j = 0; j < 8; j++) {
                float hv = h[j];
                hv = fmaf(hv * Ar[j], adt, fmaf(bs[j], u01, hv));
                h[j] = hv;
                float p = hv * cs[j];
                if (j & 1) p1 += p; else p0 += p;
            }
            float part = p0 + p1;
            float tot = part + __shfl_xor_sync(0xffffffffu, part, 16);
            if (!half)
                yout[((size_t)b * SEQ + tcg + tt) * D_INNER + d] = Dd * u + tot;
        }
        __syncthreads();
    }
}

// ---------------- gate multiply -> split bf16 y (4 elems/thread) ----------------
__global__ void gate_mul(const float* __restrict__ y, const float* __restrict__ xp,
                         __nv_bfloat16* __restrict__ yhi,
                         __nv_bfloat16* __restrict__ ylo) {
    int i = blockIdx.x * 256 + threadIdx.x;        // quad index, NTOK*D_INNER/4
    int row = i / (D_INNER / 4);
    int dq  = i - row * (D_INNER / 4);
    float4 yv = ((const float4*)y)[i];
    const float4 gv = *(const float4*)&xp[(size_t)row * (2 * D_INNER) + D_INNER + dq * 4];
    float ya[4] = {yv.x, yv.y, yv.z, yv.w};
    float ga[4] = {gv.x, gv.y, gv.z, gv.w};
    float hf[4], lf[4];
#pragma unroll
    for (int j = 0; j < 4; j++) {
        float v = ya[j] * (1.f / (1.f + expf(-ga[j])));
        __nv_bfloat16 hb = __float2bfloat16(v);
        hf[j] = __bfloat162float(hb);
        lf[j] = v - hf[j];
    }
    ((uint2*)yhi)[i] = make_uint2(pack_bf2(hf[0], hf[1]), pack_bf2(hf[2], hf[3]));
    ((uint2*)ylo)[i] = make_uint2(pack_bf2(lf[0], lf[1]), pack_bf2(lf[2], lf[3]));
}

// -------- layernorm: out = post? + LN(in + res?) * g + b (+ bf16/fp16 emit) --------
__device__ __forceinline__ float block_reduce(float v, float* red) {
    for (int o = 16; o > 0; o >>= 1) v += __shfl_down_sync(0xffffffffu, v, o);
    if ((threadIdx.x & 31) == 0) red[threadIdx.x >> 5] = v;
    __syncthreads();
    float t = 0.f;
#pragma unroll
    for (int w = 0; w < 8; w++) t += red[w];
    return t;
}

__global__ __launch_bounds__(256)
void ln_kernel(const float* __restrict__ in, const float* __restrict__ res,
               const float* __restrict__ post,
               const float* __restrict__ g, const float* __restrict__ b,
               float* __restrict__ out,
               __nv_bfloat16* __restrict__ ohi, __nv_bfloat16* __restrict__ olo,
               __half* __restrict__ of16) {
    __shared__ float red[8];
    const int row = blockIdx.x;
    const int t   = threadIdx.x;
    float v[3], pv[3];
    float s = 0.f;
#pragma unroll
    for (int i = 0; i < 3; i++) {
        int c = t + i * 256;
        float x = in[(size_t)row * D_MODEL + c];
        if (res) x += res[(size_t)row * D_MODEL + c];
        pv[i] = post ? post[(size_t)row * D_MODEL + c] : 0.f;
        v[i] = x;
        s += x;
    }
    float tot = block_reduce(s, red);
    float mu = tot * (1.f / D_MODEL);
    __syncthreads();
    float q = 0.f;
#pragma unroll
    for (int i = 0; i < 3; i++) {
        float dd = v[i] - mu;
        q += dd * dd;
    }
    float qtot = block_reduce(q, red);
    float rs = rsqrtf(qtot * (1.f / D_MODEL) + LN_EPS);
#pragma unroll
    for (int i = 0; i < 3; i++) {
        int c = t + i * 256;
        float o = pv[i] + (v[i] - mu) * rs * g[c] + b[c];
        size_t idx = (size_t)row * D_MODEL + c;
        out[idx] = o;
        if (ohi) {
            __nv_bfloat16 h = __float2bfloat16(o);
            ohi[idx] = h;
            olo[idx] = __float2bfloat16(o - __bfloat162float(h));
        }
        if (of16) of16[idx] = __float2half(o);
    }
}

// ---------------- launch ----------------
extern "C" void kernel_launch(void* const* d_in, const int* in_sizes, int n_in,
                              void* d_out, int out_size) {
    const int*   input_ids = (const int*)  d_in[0];
    const float* emb       = (const float*)d_in[1];
    const float* W_in      = (const float*)d_in[2];   // [2, 3072, 768]
    const float* W_dt      = (const float*)d_in[3];   // [2, 1536, 768]
    const float* b_dt      = (const float*)d_in[4];
    const float* dt_bias   = (const float*)d_in[5];
    const float* W_B       = (const float*)d_in[6];
    const float* W_C       = (const float*)d_in[7];
    const float* Amat      = (const float*)d_in[8];
    const float* Dvec      = (const float*)d_in[9];
    const float* W_out     = (const float*)d_in[10];  // [2, 768, 1536]
    const float* ln_g      = (const float*)d_in[11];
    const float* ln_b      = (const float*)d_in[12];
    const float* fin_g     = (const float*)d_in[13];
    const float* fin_b     = (const float*)d_in[14];
    float* logits = (float*)d_out;                    // [4096, 32000]

    float *x, *xp, *dt, *Bm, *Cm, *y, *o;
    __nv_bfloat16 *xhi, *xlo, *yhi, *ylo;
    __nv_bfloat16 *wihi, *wilo, *wdhi, *wdlo, *wohi, *wolo;
    __half *xf16, *ehi, *elo;
    cudaGetSymbolAddress((void**)&x,  g_x);
    cudaGetSymbolAddress((void**)&xp, g_xp);
    cudaGetSymbolAddress((void**)&dt, g_dt);
    cudaGetSymbolAddress((void**)&Bm, g_Bm);
    cudaGetSymbolAddress((void**)&Cm, g_Cm);
    cudaGetSymbolAddress((void**)&y,  g_y);
    cudaGetSymbolAddress((void**)&o,  g_o);
    cudaGetSymbolAddress((void**)&xhi, g_xhi);
    cudaGetSymbolAddress((void**)&xlo, g_xlo);
    cudaGetSymbolAddress((void**)&yhi, g_yhi);
    cudaGetSymbolAddress((void**)&ylo, g_ylo);
    cudaGetSymbolAddress((void**)&wihi, g_wihi);
    cudaGetSymbolAddress((void**)&wilo, g_wilo);
    cudaGetSymbolAddress((void**)&wdhi, g_wdhi);
    cudaGetSymbolAddress((void**)&wdlo, g_wdlo);
    cudaGetSymbolAddress((void**)&wohi, g_wohi);
    cudaGetSymbolAddress((void**)&wolo, g_wolo);
    cudaGetSymbolAddress((void**)&xf16, g_xf16);
    cudaGetSymbolAddress((void**)&ehi, g_ehi);
    cudaGetSymbolAddress((void**)&elo, g_elo);

    cudaFuncSetAttribute(gemm_split, cudaFuncAttributeMaxDynamicSharedMemorySize,
                         GEMM_SMEM);
    cudaFuncSetAttribute(gemm_fp16_2t, cudaFuncAttributeMaxDynamicSharedMemorySize,
                         GEMM16_SMEM);

    embed_kernel<<<NTOK, D_MODEL / 4>>>(input_ids, emb, x, xhi, xlo);

    // hoisted weight/emb splits (vectorized, dedicated buffers)
    {
        int n4 = N_LAYERS * 2 * D_INNER * D_MODEL / 4;
        split_kernel<<<(n4 + 255) / 256, 256>>>(W_in, wihi, wilo, n4);
        n4 = N_LAYERS * D_INNER * D_MODEL / 4;
        split_kernel<<<(n4 + 255) / 256, 256>>>(W_dt, wdhi, wdlo, n4);
        n4 = N_LAYERS * D_MODEL * D_INNER / 4;
        split_kernel<<<(n4 + 255) / 256, 256>>>(W_out, wohi, wolo, n4);
        n4 = VOCAB * D_MODEL / 4;
        split_fp16_kernel<<<(n4 + 255) / 256, 256>>>(emb, ehi, elo, n4);
    }

    for (int l = 0; l < N_LAYERS; l++) {
        const size_t oWi = (size_t)l * 2 * D_INNER * D_MODEL;
        const size_t oWd = (size_t)l * D_INNER * D_MODEL;
        const size_t oWo = (size_t)l * D_MODEL * D_INNER;
        const float* bd = b_dt    + (size_t)l * D_INNER;
        const float* db = dt_bias + (size_t)l * D_INNER;
        const float* Wb = W_B   + (size_t)l * D_STATE * D_MODEL;
        const float* Wc = W_C   + (size_t)l * D_STATE * D_MODEL;
        const float* Al = Amat  + (size_t)l * D_INNER * D_STATE;
        const float* Dl = Dvec  + (size_t)l * D_INNER;
        const float* lg = ln_g  + (size_t)l * D_MODEL;
        const float* lb = ln_b  + (size_t)l * D_MODEL;

        // xp = x @ W_in^T : [4096, 3072]
        gemm_split<<<dim3(NTOK / 128, 2 * D_INNER / 128), 256, GEMM_SMEM>>>(
            xhi, xlo, wihi + oWi, wilo + oWi, xp, NTOK, 2 * D_INNER, D_MODEL,
            0, nullptr, nullptr);
        // dt = softplus/clip(x @ W_dt^T + biases) fused in epilogue
        gemm_split<<<dim3(NTOK / 128, D_INNER / 128), 256, GEMM_SMEM>>>(
            xhi, xlo, wdhi + oWd, wdlo + oWd, dt, NTOK, D_INNER, D_MODEL,
            1, bd, db);
        bc_gemm<<<NTOK / 8, 256>>>(x, Wb, Wc, Bm, Cm);
        ssm_scan<<<dim3(D_INNER / 64, BATCH), 128>>>(xp, dt, Bm, Cm, Al, Dl, y);
        gate_mul<<<NTOK * D_INNER / 4 / 256, 256>>>(y, xp, yhi, ylo);
        // o = (y*gate) @ W_out^T : [4096, 768], K=1536
        gemm_split<<<dim3(NTOK / 128, D_MODEL / 128), 256, GEMM_SMEM>>>(
            yhi, ylo, wohi + oWo, wolo + oWo, o, NTOK, D_MODEL, D_INNER,
            0, nullptr, nullptr);
        // x <- x + LN(o + x)  (emit bf16 split x for next layer's GEMMs)
        ln_kernel<<<NTOK, 256>>>(o, x, x, lg, lb, x, xhi, xlo, nullptr);
    }

    // final LN (emit fp16 x for logits GEMM)
    ln_kernel<<<NTOK, 256>>>(x, nullptr, nullptr, fin_g, fin_b, x,
                             nullptr, nullptr, xf16);
    // logits = x @ emb^T : [4096, 32000]  (fp16 one-sided 2-term)
    gemm_fp16_2t<<<dim3(NTOK / 128, VOCAB / 128), 256, GEMM16_SMEM>>>(
        xf16, ehi, elo, logits, NTOK, VOCAB, D_MODEL);
}